// round 14
// baseline (speedup 1.0000x reference)
#include <cuda_runtime.h>

#define NN 50000
#define EE 800000
#define ET 850000   // EE + NN self loops
#define CAP 96      // padded adjacency capacity (deg ~ Poisson(16)+1; P(>95) ~ 0)

// ---------------- scratch (static device globals; no allocation) ----------------
__device__ __align__(16) float g_xl[NN * 128];
__device__ __align__(16) float g_xr[NN * 128];
__device__ __align__(16) float g_ha[NN * 128];
__device__ __align__(16) float g_hb[NN * 128];
__device__ int   g_cnt[NN];          // per-node cursor / degree
__device__ int   g_adj[NN * CAP];    // padded adjacency (src lists by dst)
// concatenated padded weights: L0 [32][256] @0, L1 [128][256] @8192, L2 [128][64] @40960
__device__ __align__(16) float g_wcat[49152];

#define OFF_WC0 0
#define OFF_WC1 8192
#define OFF_WC2 40960

// ---------------- weight repack: Wcat = [Wl | Wr], K zero-padded ----------------
__global__ void k_repack(const float* __restrict__ W0l, const float* __restrict__ W0r,
                         const float* __restrict__ W1l, const float* __restrict__ W1r,
                         const float* __restrict__ W2l, const float* __restrict__ W2r) {
    int i = blockIdx.x * blockDim.x + threadIdx.x;
    if (i >= 49152) return;
    float v = 0.f;
    if (i < 8192) {                       // L0: KPAD=32, MCAT=256, KREAL=18
        int k = i >> 8, c = i & 255;
        if (k < 18) v = (c < 128) ? W0l[k * 128 + c] : W0r[k * 128 + (c - 128)];
        g_wcat[OFF_WC0 + i] = v;
    } else if (i < 40960) {               // L1: K=128, MCAT=256
        int j = i - 8192;
        int k = j >> 8, c = j & 255;
        v = (c < 128) ? W1l[k * 128 + c] : W1r[k * 128 + (c - 128)];
        g_wcat[i] = v;
    } else {                              // L2: K=128, MCAT=64
        int j = i - 40960;
        int k = j >> 6, c = j & 63;
        v = (c < 32) ? W2l[k * 32 + c] : W2r[k * 32 + (c - 32)];
        g_wcat[i] = v;
    }
}

// ---------------- padded CSR build (by dst): memset + single scatter ----------------
__global__ void k_scatter_pad(const int* __restrict__ ei) {
    int e = blockIdx.x * blockDim.x + threadIdx.x;
    if (e >= ET) return;
    int src, dst;
    if (e < EE) { src = ei[e]; dst = ei[EE + e]; }
    else        { src = e - EE; dst = e - EE; }
    int pos = atomicAdd(&g_cnt[dst], 1);
    if (pos < CAP) g_adj[dst * CAP + pos] = src;
}

// ---------------- raw tf32 mma / cp.async helpers ----------------
__device__ __forceinline__ unsigned f2tf(float v) {
    unsigned u; asm("cvt.rna.tf32.f32 %0, %1;" : "=r"(u) : "f"(v)); return u;
}
__device__ __forceinline__ void mma_tf32(float* c, const unsigned* a, const unsigned* b) {
    asm("mma.sync.aligned.m16n8k8.row.col.f32.tf32.tf32.f32 "
        "{%0,%1,%2,%3},{%4,%5,%6,%7},{%8,%9},{%0,%1,%2,%3};"
        : "+f"(c[0]), "+f"(c[1]), "+f"(c[2]), "+f"(c[3])
        : "r"(a[0]), "r"(a[1]), "r"(a[2]), "r"(a[3]), "r"(b[0]), "r"(b[1]));
}
__device__ __forceinline__ void cp16(unsigned dst, const void* src, int src_bytes) {
    asm volatile("cp.async.ca.shared.global [%0], [%1], 16, %2;"
                 :: "r"(dst), "l"(src), "r"(src_bytes));
}
__device__ __forceinline__ void cp_commit() { asm volatile("cp.async.commit_group;"); }
template<int N>
__device__ __forceinline__ void cp_wait() {
    asm volatile("cp.async.wait_group %0;" :: "n"(N) : "memory");
}

// ---------------- tf32 mma dual GEMM, cp.async double-buffered ----------------
// out1[n,MOUT] | out2[n,MOUT] = in[n,KREAL] @ Wcat[KPAD, MCAT] + b1|b2  (MCAT=2*MOUT)
// block = 4 warps (2 row x 2 col), block tile 64 rows x 64 cols, warp tile 32x32.
// A staged 64x32/chunk stride 36, B staged 32x64/chunk stride 72 (both bijective
// bank maps); raw f32 in smem, tf32 conversion at fragment load.
template<int KREAL, int KPAD, int MCAT, int MOUT>
__global__ void k_lins(const float* __restrict__ in, const float* __restrict__ W,
                       const float* __restrict__ b1, const float* __restrict__ b2,
                       float* __restrict__ out1, float* __restrict__ out2, int nrows) {
    constexpr int NC = KPAD / 32;           // 32-k chunks
    __shared__ float A_s[2][64 * 36];       // 18 KB
    __shared__ float B_s[2][32 * 72];       // 18 KB
    int tid  = threadIdx.x;                  // 128 threads
    int lane = tid & 31;
    int wid  = tid >> 5;
    int gid  = lane >> 2;
    int tig  = lane & 3;
    int wcol = wid & 1, wrow = wid >> 1;
    int row0 = blockIdx.x * 64;
    int colb = blockIdx.y * 64;

    float acc[2][4][4];
#pragma unroll
    for (int mi = 0; mi < 2; mi++)
#pragma unroll
        for (int ni = 0; ni < 4; ni++)
#pragma unroll
            for (int q = 0; q < 4; q++) acc[mi][ni][q] = 0.f;

    // ---- stage fill: chunk kc -> stage st ----
    auto fill = [&](int st, int kc) {
        if ((KREAL & 3) == 0) {
            // cp.async path: A 64x32 = 512 f4, B 32x64 = 512 f4; 4+4 per thread
#pragma unroll
            for (int q = tid; q < 512; q += 128) {
                int r = q >> 3, c4 = (q & 7) << 2;
                int gr = row0 + r;
                const float* src = in + (long)gr * KREAL + kc + c4;
                unsigned dst = (unsigned)__cvta_generic_to_shared(&A_s[st][r * 36 + c4]);
                cp16(dst, src, (gr < nrows) ? 16 : 0);
            }
#pragma unroll
            for (int q = tid; q < 512; q += 128) {
                int r = q >> 4, c4 = (q & 15) << 2;
                const float* src = W + (long)(kc + r) * MCAT + colb + c4;
                unsigned dst = (unsigned)__cvta_generic_to_shared(&B_s[st][r * 72 + c4]);
                cp16(dst, src, 16);
            }
        } else {
            // scalar guarded path (lin0: KREAL=18)
            for (int q = tid; q < 2048; q += 128) {
                int r = q >> 5, c = q & 31;
                int gr = row0 + r, gc = kc + c;
                A_s[st][r * 36 + c] =
                    (gr < nrows && gc < KREAL) ? __ldg(in + (long)gr * KREAL + gc) : 0.f;
            }
            for (int q = tid; q < 512; q += 128) {
                int r = q >> 4, c4 = (q & 15) << 2;
                *(float4*)&B_s[st][r * 72 + c4] =
                    __ldg((const float4*)(W + (long)(kc + r) * MCAT + colb + c4));
            }
        }
    };

    fill(0, 0);
    if ((KREAL & 3) == 0) cp_commit();

    for (int c = 0; c < NC; c++) {
        if ((KREAL & 3) == 0) {
            if (c + 1 < NC) {
                fill((c + 1) & 1, (c + 1) * 32);
                cp_commit();
                cp_wait<1>();
            } else {
                cp_wait<0>();
            }
        }
        __syncthreads();

        const float* As = A_s[c & 1];
        const float* Bs = B_s[c & 1];
#pragma unroll
        for (int ks = 0; ks < 4; ks++) {
            int kk = ks * 8;
            unsigned A[2][4], B[4][2];
#pragma unroll
            for (int mi = 0; mi < 2; mi++) {
                int lr = wrow * 32 + mi * 16 + gid;
                A[mi][0] = f2tf(As[lr * 36 + kk + tig]);
                A[mi][1] = f2tf(As[(lr + 8) * 36 + kk + tig]);
                A[mi][2] = f2tf(As[lr * 36 + kk + tig + 4]);
                A[mi][3] = f2tf(As[(lr + 8) * 36 + kk + tig + 4]);
            }
#pragma unroll
            for (int ni = 0; ni < 4; ni++) {
                int bn = wcol * 32 + ni * 8 + gid;
                B[ni][0] = f2tf(Bs[(kk + tig) * 72 + bn]);
                B[ni][1] = f2tf(Bs[(kk + tig + 4) * 72 + bn]);
            }
#pragma unroll
            for (int mi = 0; mi < 2; mi++)
#pragma unroll
                for (int ni = 0; ni < 4; ni++)
                    mma_tf32(acc[mi][ni], A[mi], B[ni]);
        }
        __syncthreads();
    }

    // ---- epilogue: bias + route to out1/out2 ----
#pragma unroll
    for (int mi = 0; mi < 2; mi++) {
        int rowm = row0 + wrow * 32 + mi * 16 + gid;
#pragma unroll
        for (int ni = 0; ni < 4; ni++) {
            int col = colb + wcol * 32 + ni * 8 + tig * 2;
#pragma unroll
            for (int h = 0; h < 2; h++) {
                int row = rowm + h * 8;
                if (row >= nrows) continue;
                float vx = acc[mi][ni][h * 2], vy = acc[mi][ni][h * 2 + 1];
                if (col < MOUT) {
                    float2 bb = *(const float2*)(b1 + col);
                    *(float2*)(out1 + (long)row * MOUT + col) =
                        make_float2(vx + bb.x, vy + bb.y);
                } else {
                    float2 bb = *(const float2*)(b2 + col - MOUT);
                    *(float2*)(out2 + (long)row * MOUT + col - MOUT) =
                        make_float2(vx + bb.x, vy + bb.y);
                }
            }
        }
    }
}

// ---------------- warp helpers ----------------
__device__ __forceinline__ float warp_sum(float v) {
#pragma unroll
    for (int o = 16; o > 0; o >>= 1) v += __shfl_xor_sync(0xffffffffu, v, o);
    return v;
}

#define LOG2E 1.4426950408889634f

// ---------------- fused GATv2 layer (HD=128, H=4) — rolling prefetch + exp2 ----------
template<bool RES>
__global__ void __launch_bounds__(256, 6)
k_gat128(const float* __restrict__ xl, const float* __restrict__ xr,
         const float* __restrict__ att,
         const float* __restrict__ bo, const float* __restrict__ gg,
         const float* __restrict__ be, const float* __restrict__ resid,
         float* __restrict__ out) {
    int node = (blockIdx.x * blockDim.x + threadIdx.x) >> 5;
    int lane = threadIdx.x & 31;
    if (node >= NN) return;
    int deg = g_cnt[node];
    const int* adj = g_adj + (long)node * CAP;

    float4 xr4 = *(const float4*)(xr + (long)node * 128 + (lane << 2));
    float4 at4 = __ldg((const float4*)(att + (lane << 2)));
    at4.x *= LOG2E; at4.y *= LOG2E; at4.z *= LOG2E; at4.w *= LOG2E;  // fold into dot

    float den = 0.f;
    float ax = 0.f, ay = 0.f, az = 0.f, aw = 0.f;

    for (int base = 0; base < deg; base += 32) {
        int rem = deg - base;
        int n = rem > 32 ? 32 : rem;
        int s = adj[base + ((lane < n) ? lane : 0)];
        int s0 = __shfl_sync(0xffffffffu, s, 0);
        int s1 = __shfl_sync(0xffffffffu, s, (n > 1) ? 1 : 0);
        float4 v0 = *(const float4*)(xl + (long)s0 * 128 + (lane << 2));
        float4 v1 = *(const float4*)(xl + (long)s1 * 128 + (lane << 2));
#pragma unroll 4
        for (int j = 0; j < n; j++) {
            float4 vc = v0;
            v0 = v1;
            int j2 = j + 2; j2 = (j2 < n) ? j2 : (n - 1);
            int sn = __shfl_sync(0xffffffffu, s, j2);
            v1 = *(const float4*)(xl + (long)sn * 128 + (lane << 2));

            float t0 = vc.x + xr4.x; t0 = fmaxf(t0, 0.2f * t0);
            float t1 = vc.y + xr4.y; t1 = fmaxf(t1, 0.2f * t1);
            float t2 = vc.z + xr4.z; t2 = fmaxf(t2, 0.2f * t2);
            float t3 = vc.w + xr4.w; t3 = fmaxf(t3, 0.2f * t3);
            float p = fmaf(t0, at4.x, fmaf(t1, at4.y, fmaf(t2, at4.z, t3 * at4.w)));
            p += __shfl_xor_sync(0xffffffffu, p, 1);
            p += __shfl_xor_sync(0xffffffffu, p, 2);
            p += __shfl_xor_sync(0xffffffffu, p, 4);
            float a = exp2f(fminf(p, 100.f));   // base-2 softmax (att pre-scaled)
            ax = fmaf(a, vc.x, ax); ay = fmaf(a, vc.y, ay);
            az = fmaf(a, vc.z, az); aw = fmaf(a, vc.w, aw);
            den += a;
        }
    }

    float inv = 1.f / den;
    float4 bo4 = __ldg((const float4*)(bo + (lane << 2)));
    float o0 = ax * inv + bo4.x;
    float o1 = ay * inv + bo4.y;
    float o2 = az * inv + bo4.z;
    float o3 = aw * inv + bo4.w;

    float mean = warp_sum(o0 + o1 + o2 + o3) * (1.f / 128.f);
    float e0 = o0 - mean, e1 = o1 - mean, e2 = o2 - mean, e3 = o3 - mean;
    float var = warp_sum(e0 * e0 + e1 * e1 + e2 * e2 + e3 * e3) * (1.f / 128.f);
    float rinv = rsqrtf(var + 1e-5f);
    float4 g4  = __ldg((const float4*)(gg + (lane << 2)));
    float4 be4 = __ldg((const float4*)(be + (lane << 2)));
    float v0 = e0 * rinv * g4.x + be4.x;
    float v1 = e1 * rinv * g4.y + be4.y;
    float v2 = e2 * rinv * g4.z + be4.z;
    float v3 = e3 * rinv * g4.w + be4.w;
    v0 = (v0 > 0.f) ? v0 : (__expf(v0) - 1.f);
    v1 = (v1 > 0.f) ? v1 : (__expf(v1) - 1.f);
    v2 = (v2 > 0.f) ? v2 : (__expf(v2) - 1.f);
    v3 = (v3 > 0.f) ? v3 : (__expf(v3) - 1.f);
    if (RES) {
        float4 r4 = *(const float4*)(resid + (long)node * 128 + (lane << 2));
        v0 += r4.x; v1 += r4.y; v2 += r4.z; v3 += r4.w;
    }
    *(float4*)(out + (long)node * 128 + (lane << 2)) = make_float4(v0, v1, v2, v3);
}

// ---------------- layer-2 (HD=32, H=1) fused with final MLP ----------------
__global__ void __launch_bounds__(256, 6)
k_gat_final(const float* __restrict__ xl, const float* __restrict__ xr,
            const float* __restrict__ att,
            const float* __restrict__ bo, const float* __restrict__ gg,
            const float* __restrict__ be,
            const float* __restrict__ cW1, const float* __restrict__ cb1,
            const float* __restrict__ cW2, const float* __restrict__ cb2,
            float* __restrict__ out) {
    __shared__ float sh[8][32];
    int node = (blockIdx.x * blockDim.x + threadIdx.x) >> 5;
    int lane = threadIdx.x & 31;
    int wib  = threadIdx.x >> 5;
    if (node >= NN) return;
    int deg = g_cnt[node];
    const int* adj = g_adj + (long)node * CAP;

    float xrv = xr[(long)node * 32 + lane];
    float atv = __ldg(&att[lane]) * LOG2E;

    float den = 0.f, acc = 0.f;
    for (int base = 0; base < deg; base += 32) {
        int rem = deg - base;
        int n = rem > 32 ? 32 : rem;
        int s = adj[base + ((lane < n) ? lane : 0)];
        int s0 = __shfl_sync(0xffffffffu, s, 0);
        int s1 = __shfl_sync(0xffffffffu, s, (n > 1) ? 1 : 0);
        float v0 = xl[(long)s0 * 32 + lane];
        float v1 = xl[(long)s1 * 32 + lane];
#pragma unroll 4
        for (int j = 0; j < n; j++) {
            float vc = v0;
            v0 = v1;
            int j2 = j + 2; j2 = (j2 < n) ? j2 : (n - 1);
            int sn = __shfl_sync(0xffffffffu, s, j2);
            v1 = xl[(long)sn * 32 + lane];

            float t = vc + xrv; t = fmaxf(t, 0.2f * t);
            float p = warp_sum(t * atv);
            float a = exp2f(fminf(p, 100.f));
            acc = fmaf(a, vc, acc);
            den += a;
        }
    }
    float o = acc / den + bo[lane];

    float mean = warp_sum(o) * (1.f / 32.f);
    float ec = o - mean;
    float var = warp_sum(ec * ec) * (1.f / 32.f);
    float v = ec * rsqrtf(var + 1e-5f) * gg[lane] + be[lane];
    v = (v > 0.f) ? v : (__expf(v) - 1.f);   // ELU

    sh[wib][lane] = v;
    __syncwarp();

    float r = 0.f;
    if (lane < 16) {
        float c = cb1[lane];
#pragma unroll
        for (int j = 0; j < 32; j++) c += sh[wib][j] * cW1[j * 16 + lane];
        c = (c > 0.f) ? c : (__expf(c) - 1.f);   // ELU
        r = c * cW2[lane];
    }
#pragma unroll
    for (int o2 = 8; o2 > 0; o2 >>= 1) r += __shfl_xor_sync(0xffffffffu, r, o2);
    if (lane == 0) out[node] = r + cb2[0];
}

// ---------------- host ----------------
extern "C" void kernel_launch(void* const* d_in, const int* in_sizes, int n_in,
                              void* d_out, int out_size) {
    const float* x    = (const float*)d_in[0];
    const int*   ei   = (const int*)  d_in[1];
    const float* Wl0  = (const float*)d_in[2];  const float* bl0 = (const float*)d_in[3];
    const float* Wr0  = (const float*)d_in[4];  const float* br0 = (const float*)d_in[5];
    const float* att0 = (const float*)d_in[6];  const float* bo0 = (const float*)d_in[7];
    const float* g0   = (const float*)d_in[8];  const float* be0 = (const float*)d_in[9];
    const float* Wl1  = (const float*)d_in[10]; const float* bl1 = (const float*)d_in[11];
    const float* Wr1  = (const float*)d_in[12]; const float* br1 = (const float*)d_in[13];
    const float* att1 = (const float*)d_in[14]; const float* bo1 = (const float*)d_in[15];
    const float* g1   = (const float*)d_in[16]; const float* be1 = (const float*)d_in[17];
    const float* Wl2  = (const float*)d_in[18]; const float* bl2 = (const float*)d_in[19];
    const float* Wr2  = (const float*)d_in[20]; const float* br2 = (const float*)d_in[21];
    const float* att2 = (const float*)d_in[22]; const float* bo2 = (const float*)d_in[23];
    const float* g2   = (const float*)d_in[24]; const float* be2 = (const float*)d_in[25];
    const float* cW1  = (const float*)d_in[26]; const float* cb1 = (const float*)d_in[27];
    const float* cW2  = (const float*)d_in[28]; const float* cb2 = (const float*)d_in[29];
    float* out = (float*)d_out;

    float *xl, *xr, *ha, *hb, *wc;
    int* cnt;
    cudaGetSymbolAddress((void**)&xl, g_xl);
    cudaGetSymbolAddress((void**)&xr, g_xr);
    cudaGetSymbolAddress((void**)&ha, g_ha);
    cudaGetSymbolAddress((void**)&hb, g_hb);
    cudaGetSymbolAddress((void**)&wc, g_wcat);
    cudaGetSymbolAddress((void**)&cnt, g_cnt);

    const int EB = (ET + 255) / 256;        // thread-per-edge blocks
    const int NW = (NN + 7) / 8;            // warp-per-node blocks (256 thr = 8 warps)
    const int RB = (NN + 63) / 64;          // 64-row GEMM blocks

    // weight repack + CSR build (independent)
    k_repack<<<(49152 + 255) / 256, 256>>>(Wl0, Wr0, Wl1, Wr1, Wl2, Wr2);
    cudaMemsetAsync(cnt, 0, NN * sizeof(int));
    k_scatter_pad<<<EB, 256>>>(ei);

    // ---- layer 0 ----  (KREAL=18, KPAD=32: one zero-padded chunk, scalar path)
    k_lins<18, 32, 256, 128><<<dim3(RB, 4), 128>>>(x, wc + OFF_WC0, bl0, br0, xl, xr, NN);
    k_gat128<false><<<NW, 256>>>(xl, xr, att0, bo0, g0, be0, (const float*)0, ha);

    // ---- layer 1 (residual) ----
    k_lins<128, 128, 256, 128><<<dim3(RB, 4), 128>>>(ha, wc + OFF_WC1, bl1, br1, xl, xr, NN);
    k_gat128<true><<<NW, 256>>>(xl, xr, att1, bo1, g1, be1, ha, hb);

    // ---- layer 2 (H=1, D=32) + classifier MLP ----
    k_lins<128, 128, 64, 32><<<dim3(RB, 1), 128>>>(hb, wc + OFF_WC2, bl2, br2, xl, xr, NN);
    k_gat_final<<<NW, 256>>>(xl, xr, att2, bo2, g2, be2, cW1, cb1, cW2, cb2, out);
}

// round 15
// speedup vs baseline: 1.0965x; 1.0965x over previous
#include <cuda_runtime.h>

#define NN 50000
#define EE 800000
#define ET 850000   // EE + NN self loops
#define CAP 96      // padded adjacency capacity (deg ~ Poisson(16)+1; P(>95) ~ 0)

// ---------------- scratch (static device globals; no allocation) ----------------
__device__ __align__(16) float g_xl[NN * 128];
__device__ __align__(16) float g_xr[NN * 128];
__device__ __align__(16) float g_ha[NN * 128];
__device__ __align__(16) float g_hb[NN * 128];
__device__ int   g_cnt[NN];          // per-node cursor / degree
__device__ int   g_adj[NN * CAP];    // padded adjacency (src lists by dst)
// concatenated padded weights: L0 [32][256] @0, L1 [128][256] @8192, L2 [128][64] @40960
__device__ __align__(16) float g_wcat[49152];

#define OFF_WC0 0
#define OFF_WC1 8192
#define OFF_WC2 40960

// ---------------- weight repack + g_cnt zero (fused: keeps lin1 at launch #5) -------
__global__ void k_repack(const float* __restrict__ W0l, const float* __restrict__ W0r,
                         const float* __restrict__ W1l, const float* __restrict__ W1r,
                         const float* __restrict__ W2l, const float* __restrict__ W2r) {
    int i = blockIdx.x * blockDim.x + threadIdx.x;
    if (i < NN) g_cnt[i] = 0;
    if (i >= 49152) return;
    float v = 0.f;
    if (i < 8192) {                       // L0: KPAD=32, MCAT=256, KREAL=18
        int k = i >> 8, c = i & 255;
        if (k < 18) v = (c < 128) ? W0l[k * 128 + c] : W0r[k * 128 + (c - 128)];
        g_wcat[OFF_WC0 + i] = v;
    } else if (i < 40960) {               // L1: K=128, MCAT=256
        int j = i - 8192;
        int k = j >> 8, c = j & 255;
        v = (c < 128) ? W1l[k * 128 + c] : W1r[k * 128 + (c - 128)];
        g_wcat[i] = v;
    } else {                              // L2: K=128, MCAT=64
        int j = i - 40960;
        int k = j >> 6, c = j & 63;
        v = (c < 32) ? W2l[k * 32 + c] : W2r[k * 32 + (c - 32)];
        g_wcat[i] = v;
    }
}

// ---------------- padded CSR build (by dst): single scatter (cnt zeroed in repack) --
__global__ void k_scatter_pad(const int* __restrict__ ei) {
    int e = blockIdx.x * blockDim.x + threadIdx.x;
    if (e >= ET) return;
    int src, dst;
    if (e < EE) { src = ei[e]; dst = ei[EE + e]; }
    else        { src = e - EE; dst = e - EE; }
    int pos = atomicAdd(&g_cnt[dst], 1);
    if (pos < CAP) g_adj[dst * CAP + pos] = src;
}

// ---------------- raw tf32 mma / cp.async helpers ----------------
__device__ __forceinline__ unsigned f2tf(float v) {
    unsigned u; asm("cvt.rna.tf32.f32 %0, %1;" : "=r"(u) : "f"(v)); return u;
}
__device__ __forceinline__ void mma_tf32(float* c, const unsigned* a, const unsigned* b) {
    asm("mma.sync.aligned.m16n8k8.row.col.f32.tf32.tf32.f32 "
        "{%0,%1,%2,%3},{%4,%5,%6,%7},{%8,%9},{%0,%1,%2,%3};"
        : "+f"(c[0]), "+f"(c[1]), "+f"(c[2]), "+f"(c[3])
        : "r"(a[0]), "r"(a[1]), "r"(a[2]), "r"(a[3]), "r"(b[0]), "r"(b[1]));
}
__device__ __forceinline__ void cp16(unsigned dst, const void* src, int src_bytes) {
    asm volatile("cp.async.ca.shared.global [%0], [%1], 16, %2;"
                 :: "r"(dst), "l"(src), "r"(src_bytes));
}
__device__ __forceinline__ void cp_commit() { asm volatile("cp.async.commit_group;"); }
template<int N>
__device__ __forceinline__ void cp_wait() {
    asm volatile("cp.async.wait_group %0;" :: "n"(N) : "memory");
}

// ---------------- tf32 mma dual GEMM: 128x64 tile, A cp.async double-buffered -------
// out1[n,MOUT] | out2[n,MOUT] = in[n,KREAL] @ Wcat[KPAD, MCAT] + b1|b2  (MCAT=2*MOUT)
// block = 8 warps (4 row x 2 col), warp tile 32x32.
// A raw f32, 2 stages, stride 36 (frag LDS bank = 4*gid+tig bijective);
// B tf32, 1 stage, stride 72 (frag LDS bank = 8*tig+gid bijective). 45 KB smem.
template<int KREAL, int KPAD, int MCAT, int MOUT>
__global__ void k_lins(const float* __restrict__ in, const float* __restrict__ W,
                       const float* __restrict__ b1, const float* __restrict__ b2,
                       float* __restrict__ out1, float* __restrict__ out2, int nrows) {
    constexpr int NC = KPAD / 32;            // 32-k chunks
    constexpr bool K4 = (KREAL & 3) == 0;
    __shared__ float    A_f[2][128 * 36];    // 36 KB raw f32
    __shared__ unsigned B_s[32 * 72];        //  9 KB tf32
    int tid  = threadIdx.x;                   // 256 threads
    int lane = tid & 31;
    int wid  = tid >> 5;
    int gid  = lane >> 2;
    int tig  = lane & 3;
    int wcol = wid & 1, wrow = wid >> 1;
    int row0 = blockIdx.x * 128;
    int colb = blockIdx.y * 64;

    float acc[2][4][4];
#pragma unroll
    for (int mi = 0; mi < 2; mi++)
#pragma unroll
        for (int ni = 0; ni < 4; ni++)
#pragma unroll
            for (int q = 0; q < 4; q++) acc[mi][ni][q] = 0.f;

    // ---- A fill: chunk kc -> stage st ----
    auto fillA = [&](int st, int kc) {
        if (K4) {
#pragma unroll
            for (int i = 0; i < 4; i++) {          // 1024 float4 / 256 thr
                int q = tid + i * 256;
                int r = q >> 3, c4 = (q & 7) << 2;
                int gr = row0 + r;
                const float* src = in + (long)((gr < nrows) ? gr : 0) * KREAL + kc + c4;
                unsigned dst = (unsigned)__cvta_generic_to_shared(&A_f[st][r * 36 + c4]);
                cp16(dst, src, (gr < nrows) ? 16 : 0);
            }
        } else {
            for (int q = tid; q < 4096; q += 256) {
                int r = q >> 5, c = q & 31;
                int gr = row0 + r, gc = kc + c;
                A_f[st][r * 36 + c] =
                    (gr < nrows && gc < KREAL) ? __ldg(in + (long)gr * KREAL + gc) : 0.f;
            }
        }
    };
    // ---- B fill: chunk kc (plain LDG, tf32 at store) ----
    auto fillB = [&](int kc) {
#pragma unroll
        for (int i = 0; i < 2; i++) {              // 512 float4 / 256 thr
            int q = tid + i * 256;
            int r = q >> 4, c4 = (q & 15) << 2;
            float4 v = __ldg((const float4*)(W + (long)(kc + r) * MCAT + colb + c4));
            *(uint4*)&B_s[r * 72 + c4] =
                make_uint4(f2tf(v.x), f2tf(v.y), f2tf(v.z), f2tf(v.w));
        }
    };

    fillA(0, 0);
    if (K4) cp_commit();

    for (int c = 0; c < NC; c++) {
        fillB(c * 32);
        if (K4) {
            if (c + 1 < NC) {
                fillA((c + 1) & 1, (c + 1) * 32);
                cp_commit();
                cp_wait<1>();
            } else {
                cp_wait<0>();
            }
        }
        __syncthreads();

        const float* As = A_f[c & 1];
#pragma unroll
        for (int ks = 0; ks < 4; ks++) {
            int kk = ks * 8;
            unsigned A[2][4], B[4][2];
#pragma unroll
            for (int mi = 0; mi < 2; mi++) {
                int lr = wrow * 32 + mi * 16 + gid;
                A[mi][0] = f2tf(As[lr * 36 + kk + tig]);
                A[mi][1] = f2tf(As[(lr + 8) * 36 + kk + tig]);
                A[mi][2] = f2tf(As[lr * 36 + kk + tig + 4]);
                A[mi][3] = f2tf(As[(lr + 8) * 36 + kk + tig + 4]);
            }
#pragma unroll
            for (int ni = 0; ni < 4; ni++) {
                int bn = wcol * 32 + ni * 8 + gid;
                B[ni][0] = B_s[(kk + tig) * 72 + bn];
                B[ni][1] = B_s[(kk + tig + 4) * 72 + bn];
            }
#pragma unroll
            for (int mi = 0; mi < 2; mi++)
#pragma unroll
                for (int ni = 0; ni < 4; ni++)
                    mma_tf32(acc[mi][ni], A[mi], B[ni]);
        }
        __syncthreads();
    }

    // ---- epilogue: bias + route to out1/out2 ----
#pragma unroll
    for (int mi = 0; mi < 2; mi++) {
        int rowm = row0 + wrow * 32 + mi * 16 + gid;
#pragma unroll
        for (int ni = 0; ni < 4; ni++) {
            int col = colb + wcol * 32 + ni * 8 + tig * 2;
#pragma unroll
            for (int h = 0; h < 2; h++) {
                int row = rowm + h * 8;
                if (row >= nrows) continue;
                float vx = acc[mi][ni][h * 2], vy = acc[mi][ni][h * 2 + 1];
                if (col < MOUT) {
                    float2 bb = *(const float2*)(b1 + col);
                    *(float2*)(out1 + (long)row * MOUT + col) =
                        make_float2(vx + bb.x, vy + bb.y);
                } else {
                    float2 bb = *(const float2*)(b2 + col - MOUT);
                    *(float2*)(out2 + (long)row * MOUT + col - MOUT) =
                        make_float2(vx + bb.x, vy + bb.y);
                }
            }
        }
    }
}

// ---------------- warp helpers ----------------
__device__ __forceinline__ float warp_sum(float v) {
#pragma unroll
    for (int o = 16; o > 0; o >>= 1) v += __shfl_xor_sync(0xffffffffu, v, o);
    return v;
}

// ---------------- fused GATv2 layer (HD=128, H=4) — R13 proven version ----------
template<bool RES>
__global__ void __launch_bounds__(256, 6)
k_gat128(const float* __restrict__ xl, const float* __restrict__ xr,
         const float* __restrict__ att,
         const float* __restrict__ bo, const float* __restrict__ gg,
         const float* __restrict__ be, const float* __restrict__ resid,
         float* __restrict__ out) {
    int node = (blockIdx.x * blockDim.x + threadIdx.x) >> 5;
    int lane = threadIdx.x & 31;
    if (node >= NN) return;
    int deg = g_cnt[node];
    const int* adj = g_adj + (long)node * CAP;

    float4 xr4 = *(const float4*)(xr + (long)node * 128 + (lane << 2));
    float4 at4 = __ldg((const float4*)(att + (lane << 2)));

    float den = 0.f;
    float ax = 0.f, ay = 0.f, az = 0.f, aw = 0.f;

    for (int base = 0; base < deg; base += 32) {
        int rem = deg - base;
        int n = rem > 32 ? 32 : rem;
        int s = adj[base + ((lane < n) ? lane : 0)];
        int s0 = __shfl_sync(0xffffffffu, s, 0);
        int s1 = __shfl_sync(0xffffffffu, s, (n > 1) ? 1 : 0);
        float4 v0 = *(const float4*)(xl + (long)s0 * 128 + (lane << 2));
        float4 v1 = *(const float4*)(xl + (long)s1 * 128 + (lane << 2));
#pragma unroll 4
        for (int j = 0; j < n; j++) {
            float4 vc = v0;
            v0 = v1;
            int j2 = j + 2; j2 = (j2 < n) ? j2 : (n - 1);
            int sn = __shfl_sync(0xffffffffu, s, j2);
            v1 = *(const float4*)(xl + (long)sn * 128 + (lane << 2));

            float t0 = vc.x + xr4.x; t0 = fmaxf(t0, 0.2f * t0);
            float t1 = vc.y + xr4.y; t1 = fmaxf(t1, 0.2f * t1);
            float t2 = vc.z + xr4.z; t2 = fmaxf(t2, 0.2f * t2);
            float t3 = vc.w + xr4.w; t3 = fmaxf(t3, 0.2f * t3);
            float p = fmaf(t0, at4.x, fmaf(t1, at4.y, fmaf(t2, at4.z, t3 * at4.w)));
            p += __shfl_xor_sync(0xffffffffu, p, 1);
            p += __shfl_xor_sync(0xffffffffu, p, 2);
            p += __shfl_xor_sync(0xffffffffu, p, 4);
            float a = __expf(fminf(p, 60.f));
            ax = fmaf(a, vc.x, ax); ay = fmaf(a, vc.y, ay);
            az = fmaf(a, vc.z, az); aw = fmaf(a, vc.w, aw);
            den += a;
        }
    }

    float inv = 1.f / den;
    float4 bo4 = __ldg((const float4*)(bo + (lane << 2)));
    float o0 = ax * inv + bo4.x;
    float o1 = ay * inv + bo4.y;
    float o2 = az * inv + bo4.z;
    float o3 = aw * inv + bo4.w;

    float mean = warp_sum(o0 + o1 + o2 + o3) * (1.f / 128.f);
    float e0 = o0 - mean, e1 = o1 - mean, e2 = o2 - mean, e3 = o3 - mean;
    float var = warp_sum(e0 * e0 + e1 * e1 + e2 * e2 + e3 * e3) * (1.f / 128.f);
    float rinv = rsqrtf(var + 1e-5f);
    float4 g4  = __ldg((const float4*)(gg + (lane << 2)));
    float4 be4 = __ldg((const float4*)(be + (lane << 2)));
    float v0 = e0 * rinv * g4.x + be4.x;
    float v1 = e1 * rinv * g4.y + be4.y;
    float v2 = e2 * rinv * g4.z + be4.z;
    float v3 = e3 * rinv * g4.w + be4.w;
    v0 = (v0 > 0.f) ? v0 : (__expf(v0) - 1.f);
    v1 = (v1 > 0.f) ? v1 : (__expf(v1) - 1.f);
    v2 = (v2 > 0.f) ? v2 : (__expf(v2) - 1.f);
    v3 = (v3 > 0.f) ? v3 : (__expf(v3) - 1.f);
    if (RES) {
        float4 r4 = *(const float4*)(resid + (long)node * 128 + (lane << 2));
        v0 += r4.x; v1 += r4.y; v2 += r4.z; v3 += r4.w;
    }
    *(float4*)(out + (long)node * 128 + (lane << 2)) = make_float4(v0, v1, v2, v3);
}

// ---------------- layer-2 (HD=32, H=1) fused with final MLP ----------------
__global__ void __launch_bounds__(256, 6)
k_gat_final(const float* __restrict__ xl, const float* __restrict__ xr,
            const float* __restrict__ att,
            const float* __restrict__ bo, const float* __restrict__ gg,
            const float* __restrict__ be,
            const float* __restrict__ cW1, const float* __restrict__ cb1,
            const float* __restrict__ cW2, const float* __restrict__ cb2,
            float* __restrict__ out) {
    __shared__ float sh[8][32];
    int node = (blockIdx.x * blockDim.x + threadIdx.x) >> 5;
    int lane = threadIdx.x & 31;
    int wib  = threadIdx.x >> 5;
    if (node >= NN) return;
    int deg = g_cnt[node];
    const int* adj = g_adj + (long)node * CAP;

    float xrv = xr[(long)node * 32 + lane];
    float atv = __ldg(&att[lane]);

    float den = 0.f, acc = 0.f;
    for (int base = 0; base < deg; base += 32) {
        int rem = deg - base;
        int n = rem > 32 ? 32 : rem;
        int s = adj[base + ((lane < n) ? lane : 0)];
        int s0 = __shfl_sync(0xffffffffu, s, 0);
        int s1 = __shfl_sync(0xffffffffu, s, (n > 1) ? 1 : 0);
        float v0 = xl[(long)s0 * 32 + lane];
        float v1 = xl[(long)s1 * 32 + lane];
#pragma unroll 4
        for (int j = 0; j < n; j++) {
            float vc = v0;
            v0 = v1;
            int j2 = j + 2; j2 = (j2 < n) ? j2 : (n - 1);
            int sn = __shfl_sync(0xffffffffu, s, j2);
            v1 = xl[(long)sn * 32 + lane];

            float t = vc + xrv; t = fmaxf(t, 0.2f * t);
            float p = warp_sum(t * atv);
            float a = __expf(fminf(p, 60.f));
            acc = fmaf(a, vc, acc);
            den += a;
        }
    }
    float o = acc / den + bo[lane];

    float mean = warp_sum(o) * (1.f / 32.f);
    float ec = o - mean;
    float var = warp_sum(ec * ec) * (1.f / 32.f);
    float v = ec * rsqrtf(var + 1e-5f) * gg[lane] + be[lane];
    v = (v > 0.f) ? v : (__expf(v) - 1.f);   // ELU

    sh[wib][lane] = v;
    __syncwarp();

    float r = 0.f;
    if (lane < 16) {
        float c = cb1[lane];
#pragma unroll
        for (int j = 0; j < 32; j++) c += sh[wib][j] * cW1[j * 16 + lane];
        c = (c > 0.f) ? c : (__expf(c) - 1.f);   // ELU
        r = c * cW2[lane];
    }
#pragma unroll
    for (int o2 = 8; o2 > 0; o2 >>= 1) r += __shfl_xor_sync(0xffffffffu, r, o2);
    if (lane == 0) out[node] = r + cb2[0];
}

// ---------------- host ----------------
extern "C" void kernel_launch(void* const* d_in, const int* in_sizes, int n_in,
                              void* d_out, int out_size) {
    const float* x    = (const float*)d_in[0];
    const int*   ei   = (const int*)  d_in[1];
    const float* Wl0  = (const float*)d_in[2];  const float* bl0 = (const float*)d_in[3];
    const float* Wr0  = (const float*)d_in[4];  const float* br0 = (const float*)d_in[5];
    const float* att0 = (const float*)d_in[6];  const float* bo0 = (const float*)d_in[7];
    const float* g0   = (const float*)d_in[8];  const float* be0 = (const float*)d_in[9];
    const float* Wl1  = (const float*)d_in[10]; const float* bl1 = (const float*)d_in[11];
    const float* Wr1  = (const float*)d_in[12]; const float* br1 = (const float*)d_in[13];
    const float* att1 = (const float*)d_in[14]; const float* bo1 = (const float*)d_in[15];
    const float* g1   = (const float*)d_in[16]; const float* be1 = (const float*)d_in[17];
    const float* Wl2  = (const float*)d_in[18]; const float* bl2 = (const float*)d_in[19];
    const float* Wr2  = (const float*)d_in[20]; const float* br2 = (const float*)d_in[21];
    const float* att2 = (const float*)d_in[22]; const float* bo2 = (const float*)d_in[23];
    const float* g2   = (const float*)d_in[24]; const float* be2 = (const float*)d_in[25];
    const float* cW1  = (const float*)d_in[26]; const float* cb1 = (const float*)d_in[27];
    const float* cW2  = (const float*)d_in[28]; const float* cb2 = (const float*)d_in[29];
    float* out = (float*)d_out;

    float *xl, *xr, *ha, *hb, *wc;
    cudaGetSymbolAddress((void**)&xl, g_xl);
    cudaGetSymbolAddress((void**)&xr, g_xr);
    cudaGetSymbolAddress((void**)&ha, g_ha);
    cudaGetSymbolAddress((void**)&hb, g_hb);
    cudaGetSymbolAddress((void**)&wc, g_wcat);

    const int EB = (ET + 255) / 256;        // thread-per-edge blocks
    const int NW = (NN + 7) / 8;            // warp-per-node blocks (256 thr = 8 warps)
    const int RB = (NN + 127) / 128;        // 128-row GEMM blocks

    // launch #1: repack + zero g_cnt (fused); #2: scatter
    k_repack<<<(50048 + 255) / 256, 256>>>(Wl0, Wr0, Wl1, Wr1, Wl2, Wr2);
    k_scatter_pad<<<EB, 256>>>(ei);

    // ---- layer 0 ----  (#3 lin0, #4 gat0)
    k_lins<18, 32, 256, 128><<<dim3(RB, 4), 256>>>(x, wc + OFF_WC0, bl0, br0, xl, xr, NN);
    k_gat128<false><<<NW, 256>>>(xl, xr, att0, bo0, g0, be0, (const float*)0, ha);

    // ---- layer 1 (residual) ----  (#5 lin1 -> profiled by ncu -s 5 -c 1)
    k_lins<128, 128, 256, 128><<<dim3(RB, 4), 256>>>(ha, wc + OFF_WC1, bl1, br1, xl, xr, NN);
    k_gat128<true><<<NW, 256>>>(xl, xr, att1, bo1, g1, be1, ha, hb);

    // ---- layer 2 (H=1, D=32) + classifier MLP ----
    k_lins<128, 128, 64, 32><<<dim3(RB, 1), 256>>>(hb, wc + OFF_WC2, bl2, br2, xl, xr, NN);
    k_gat_final<<<NW, 256>>>(xl, xr, att2, bo2, g2, be2, cW1, cb1, cW2, cb2, out);
}